// round 5
// baseline (speedup 1.0000x reference)
#include <cuda_runtime.h>
#include <cstdint>

#define N_NODES 100000
#define N_EDGES 1600000
#define D_EDGE  50
#define PAD     64   // padded row stride (floats) -> 256B rows, 16B-aligned chunks

// Padded scratch accumulator (25.6 MB), float4 => guaranteed 16B alignment.
__device__ float4 g_out_pad4[(size_t)N_NODES * PAD / 4];

// 1 if receivers buffer really holds int64, 0 if it holds int32.
__device__ int g_idx_is_i64;

// ---------------------------------------------------------------------------
// Kernel 0: dtype detection. Interpret the first 2048 64-bit words of the
// receivers buffer as int64. True int64 indices are all in [0, N_NODES);
// int32 data packed pairwise (lo | hi<<32) will blow the range with
// overwhelming probability. Reads only 16 KB -> safe for either true size.
// Deterministic: same input -> same flag.
// ---------------------------------------------------------------------------
__global__ void detect_kernel(const void* __restrict__ recv) {
    __shared__ int s_bad;
    if (threadIdx.x == 0) s_bad = 0;
    __syncthreads();
    const long long* p64 = (const long long*)recv;
    int bad = 0;
    for (int i = threadIdx.x; i < 2048; i += blockDim.x) {
        long long v = p64[i];
        if (v < 0 || v >= N_NODES) bad = 1;
    }
    if (__syncthreads_or(bad)) {
        if (threadIdx.x == 0) g_idx_is_i64 = 0;
    } else {
        if (threadIdx.x == 0) g_idx_is_i64 = 1;
    }
}

// ---------------------------------------------------------------------------
// Kernel 1: zero the padded scratch (float4 stores, grid-stride)
// ---------------------------------------------------------------------------
__global__ void zero_pad_kernel() {
    const size_t n4 = (size_t)N_NODES * PAD / 4;  // 1.6M float4
    for (size_t i = (size_t)blockIdx.x * blockDim.x + threadIdx.x; i < n4;
         i += (size_t)gridDim.x * blockDim.x) {
        g_out_pad4[i] = make_float4(0.f, 0.f, 0.f, 0.f);
    }
}

// ---------------------------------------------------------------------------
// Kernel 2: scatter-add. One thread per (edge, 16B chunk). 13 chunks per edge:
// chunks 0..11 -> red.global.add.v4.f32 on floats [4c, 4c+4),
// chunk 12     -> red.global.add.v2.f32 on floats 48..49.
// Edge rows are 200B (8B aligned) -> two float2 source loads.
// Padded dest rows are 256B -> 16B-aligned v4 targets.
// ---------------------------------------------------------------------------
__global__ void scatter_kernel(const float* __restrict__ edges,
                               const void* __restrict__ recv) {
    const int idx = blockIdx.x * blockDim.x + threadIdx.x;
    const int total = N_EDGES * 13;
    if (idx >= total) return;

    const int e = idx / 13;
    const int c = idx - e * 13;

    long long r;
    if (g_idx_is_i64) {
        r = ((const long long*)recv)[e];
    } else {
        r = (long long)((const int*)recv)[e];
    }
    // Safety clamp: never fault; a wrong interpretation shows as rel_err.
    if ((unsigned long long)r >= (unsigned long long)N_NODES) return;

    const float* row = edges + (size_t)e * D_EDGE;
    float* dst = reinterpret_cast<float*>(g_out_pad4) + (size_t)r * PAD;

    if (c < 12) {
        float2 a = *reinterpret_cast<const float2*>(row + 4 * c);
        float2 b = *reinterpret_cast<const float2*>(row + 4 * c + 2);
        asm volatile("red.global.add.v4.f32 [%0], {%1, %2, %3, %4};"
                     :: "l"(dst + 4 * c), "f"(a.x), "f"(a.y), "f"(b.x), "f"(b.y)
                     : "memory");
    } else {
        float2 a = *reinterpret_cast<const float2*>(row + 48);
        asm volatile("red.global.add.v2.f32 [%0], {%1, %2};"
                     :: "l"(dst + 48), "f"(a.x), "f"(a.y)
                     : "memory");
    }
}

// ---------------------------------------------------------------------------
// Kernel 3: compact padded scratch -> dense output (initializes all of d_out).
// ---------------------------------------------------------------------------
__global__ void compact_kernel(float* __restrict__ out) {
    const int total2 = N_NODES * (D_EDGE / 2);  // 2.5M float2
    const float* pad = reinterpret_cast<const float*>(g_out_pad4);
    for (int i = blockIdx.x * blockDim.x + threadIdx.x; i < total2;
         i += gridDim.x * blockDim.x) {
        const int n = i / 25;
        const int k = i - n * 25;
        float2 v = *reinterpret_cast<const float2*>(pad + (size_t)n * PAD + 2 * k);
        reinterpret_cast<float2*>(out)[i] = v;
    }
}

extern "C" void kernel_launch(void* const* d_in, const int* in_sizes, int n_in,
                              void* d_out, int out_size) {
    // Identify inputs by element count (robust to ordering):
    //   nodes: 800,000 f32 (unused) | edges: 80,000,000 f32 | receivers: 1,600,000
    const float* edges = nullptr;
    const void* receivers = nullptr;
    for (int i = 0; i < n_in; i++) {
        if (in_sizes[i] == N_EDGES * D_EDGE) {
            edges = (const float*)d_in[i];
        } else if (in_sizes[i] == N_EDGES) {
            receivers = d_in[i];
        }
    }
    float* out = (float*)d_out;

    // 0) detect receivers dtype (int32 vs int64)
    detect_kernel<<<1, 256>>>(receivers);

    // 1) zero scratch
    zero_pad_kernel<<<2048, 256>>>();

    // 2) scatter
    const int total = N_EDGES * 13;
    const int threads = 256;
    const int blocks = (total + threads - 1) / threads;
    scatter_kernel<<<blocks, threads>>>(edges, receivers);

    // 3) compact to dense output
    compact_kernel<<<2048, 256>>>(out);
}

// round 7
// speedup vs baseline: 1.0905x; 1.0905x over previous
#include <cuda_runtime.h>
#include <cstdint>

#define N_NODES 100000
#define N_EDGES 1600000
#define D_EDGE  50

// 1 if receivers buffer really holds int64, 0 if it holds int32.
__device__ int g_idx_is_i64;

// ---------------------------------------------------------------------------
// Kernel 0: dtype detection. Interpret the first 2048 64-bit words of the
// receivers buffer as int64; true int64 indices are all in [0, N_NODES),
// int32 data packed pairwise blows the range with overwhelming probability.
// Reads 16 KB -> safe for either true buffer size. Deterministic.
// ---------------------------------------------------------------------------
__global__ void detect_kernel(const void* __restrict__ recv) {
    const long long* p64 = (const long long*)recv;
    int bad = 0;
    for (int i = threadIdx.x; i < 2048; i += blockDim.x) {
        long long v = p64[i];
        if (v < 0 || v >= N_NODES) bad = 1;
    }
    int any_bad = __syncthreads_or(bad);
    if (threadIdx.x == 0) g_idx_is_i64 = any_bad ? 0 : 1;
}

// ---------------------------------------------------------------------------
// Kernel 1: zero the output (harness poisons it to 0xAA). 20 MB, float4.
// d_out is cudaMalloc'd by the harness -> 256B aligned.
// ---------------------------------------------------------------------------
__global__ void zero_out_kernel(float4* __restrict__ out4) {
    const int n4 = N_NODES * D_EDGE / 4;  // 1,250,000
    for (int i = blockIdx.x * blockDim.x + threadIdx.x; i < n4;
         i += gridDim.x * blockDim.x) {
        out4[i] = make_float4(0.f, 0.f, 0.f, 0.f);
    }
}

// ---------------------------------------------------------------------------
// Kernel 2: scatter-add DIRECTLY into the 200B/row output, parity-phased:
// row base byte offset r*200 == (r&1)*8 (mod 16), so
//   even r: v4 chunks at float offsets 0,4,...,44  + v2 at 48
//   odd  r: v2 at 0 + v4 chunks at float offsets 2,6,...,46
// Every v4 target is 16B-aligned, every v2 target 8B-aligned.
// One thread per (edge, chunk), 13 chunks/edge. Source loads are float2
// at even float offsets of an 8B-aligned row -> always legal.
// ---------------------------------------------------------------------------
__global__ void scatter_kernel(const float* __restrict__ edges,
                               const void* __restrict__ recv,
                               float* __restrict__ out) {
    const int idx = blockIdx.x * blockDim.x + threadIdx.x;
    const int total = N_EDGES * 13;
    if (idx >= total) return;

    const int e = idx / 13;
    const int c = idx - e * 13;

    long long r;
    if (g_idx_is_i64) {
        r = ((const long long*)recv)[e];
    } else {
        r = (long long)((const int*)recv)[e];
    }
    // Safety clamp: a wrong dtype interpretation shows as rel_err, not a fault.
    if ((unsigned long long)r >= (unsigned long long)N_NODES) return;

    const float* row = edges + (size_t)e * D_EDGE;
    float* dst = out + (size_t)r * D_EDGE;
    const int odd = (int)(r & 1);

    if (c < 12) {
        const int off = 4 * c + 2 * odd;          // even -> 8B-aligned source
        float2 a = *reinterpret_cast<const float2*>(row + off);
        float2 b = *reinterpret_cast<const float2*>(row + off + 2);
        asm volatile("red.global.add.v4.f32 [%0], {%1, %2, %3, %4};"
                     :: "l"(dst + off), "f"(a.x), "f"(a.y), "f"(b.x), "f"(b.y)
                     : "memory");
    } else {
        const int off = odd ? 0 : 48;
        float2 a = *reinterpret_cast<const float2*>(row + off);
        asm volatile("red.global.add.v2.f32 [%0], {%1, %2};"
                     :: "l"(dst + off), "f"(a.x), "f"(a.y)
                     : "memory");
    }
}

extern "C" void kernel_launch(void* const* d_in, const int* in_sizes, int n_in,
                              void* d_out, int out_size) {
    // Identify inputs by element count (robust to ordering):
    //   nodes: 800,000 f32 (unused) | edges: 80,000,000 f32 | receivers: 1,600,000
    const float* edges = nullptr;
    const void* receivers = nullptr;
    for (int i = 0; i < n_in; i++) {
        if (in_sizes[i] == N_EDGES * D_EDGE) {
            edges = (const float*)d_in[i];
        } else if (in_sizes[i] == N_EDGES) {
            receivers = d_in[i];
        }
    }
    float* out = (float*)d_out;

    // 0) detect receivers dtype (int32 vs int64)
    detect_kernel<<<1, 256>>>(receivers);

    // 1) zero the output
    zero_out_kernel<<<2048, 256>>>((float4*)out);

    // 2) scatter-add straight into the output
    const int total = N_EDGES * 13;
    const int threads = 256;
    const int blocks = (total + threads - 1) / threads;
    scatter_kernel<<<blocks, threads>>>(edges, receivers, out);
}